// round 15
// baseline (speedup 1.0000x reference)
#include <cuda_runtime.h>
#include <cuda_fp16.h>
#include <cstdint>

#define BATCH   32
#define SEQLEN  4096
#define CIN     7
#define OUTC    512
#define NKERN   74
#define TB      128
#define NTILES  (BATCH * (SEQLEN / TB))   // 1024
#define GRID    296                        // 148 SMs x 2 CTAs, single wave
#define NT      256                        // 8 warps
#define WROWS   160                        // padded window rows (K padded to 32)
#define XWORDS  (CIN * WROWS)              // 1120 f16x2 words per buffer
#define PFW     5                          // ceil(1120/256) prefetch words

// out[b,t,o] = sum_{d=0}^{23} W[o,d] * x[b, t+d-22, c(o)]
// tap d: o=d-22, i=(1-o)/3, j=o+1+3i.

__device__ __forceinline__ float tapval(const float* ksm, int n, int d) {
    const int o = d - 22;
    const int i = (1 - o) / 3;
    const int j = o + 1 + 3 * i;
    return ksm[n * 24 + i * 3 + j];
}

__device__ __forceinline__ void mma16816(float& d0, float& d1, float& d2, float& d3,
                                         uint32_t a0, uint32_t a1, uint32_t a2, uint32_t a3,
                                         uint32_t b0, uint32_t b1) {
    asm volatile(
        "mma.sync.aligned.m16n8k16.row.col.f32.f16.f16.f32 "
        "{%0,%1,%2,%3}, {%4,%5,%6,%7}, {%8,%9}, {%0,%1,%2,%3};"
        : "+f"(d0), "+f"(d1), "+f"(d2), "+f"(d3)
        : "r"(a0), "r"(a1), "r"(a2), "r"(a3), "r"(b0), "r"(b1));
}

__device__ __forceinline__ uint32_t packh2(float lo, float hi) {
    __half2 h = __floats2half2_rn(lo, hi);
    return *reinterpret_cast<uint32_t*>(&h);
}

__global__ __launch_bounds__(NT, 2)
void conv_hmma(const float* __restrict__ x, const float* __restrict__ kern,
               float* __restrict__ out) {
    // xsp word u of channel c = {x_f16[u], x_f16[u+1]}  (u is window row, g = t0-22+u)
    __shared__ uint32_t xsp[2][CIN][WROWS];
    __shared__ uint32_t Bs[80][16];        // word kp of row n = {W_f16(n,2kp), W_f16(n,2kp+1)}
    __shared__ float ksm[NKERN * 24];

    const int tid  = threadIdx.x;
    const int warp = tid >> 5, lane = tid & 31;
    const int gid  = lane >> 2, tig = lane & 3;

    for (int idx = tid; idx < NKERN * 24; idx += NT) ksm[idx] = kern[idx];
    __syncthreads();

    // ---- one-time: B tile (f16, zero-padded n>=74, d>=24) ----
    for (int w = tid; w < 80 * 16; w += NT) {
        const int n = w >> 4, kp = w & 15;
        const int d0 = 2 * kp, d1 = 2 * kp + 1;
        float f0 = (n < NKERN && d0 < 24) ? tapval(ksm, n, d0) : 0.0f;
        float f1 = (n < NKERN && d1 < 24) ? tapval(ksm, n, d1) : 0.0f;
        Bs[n][kp] = packh2(f0, f1);
    }
    __syncthreads();

    // ---- one-time: all B fragments in registers (10 nb x 2 ksteps x 2 regs) ----
    uint32_t breg[10][2][2];
#pragma unroll
    for (int nb = 0; nb < 10; nb++)
#pragma unroll
        for (int ks2 = 0; ks2 < 2; ks2++) {
            breg[nb][ks2][0] = Bs[nb * 8 + gid][ks2 * 8 + tig];
            breg[nb][ks2][1] = Bs[nb * 8 + gid][ks2 * 8 + tig + 4];
        }

    // ---- one-time: load tile0 window ----
    int tile = blockIdx.x;
    {
        const int b0  = tile >> 5;
        const int t00 = (tile & 31) * TB;
        const float* xb = x + (size_t)b0 * SEQLEN * CIN;
        for (int w = tid; w < XWORDS; w += NT) {
            const int c = w / WROWS, u = w % WROWS;
            const int g = t00 - 22 + u;
            float fa = (g >= 0 && g < SEQLEN) ? xb[(size_t)g * CIN + c] : 0.0f;
            float fb = (g + 1 >= 0 && g + 1 < SEQLEN) ? xb[(size_t)(g + 1) * CIN + c] : 0.0f;
            xsp[0][c][u] = packh2(fa, fb);
        }
    }
    __syncthreads();

    int cur = 0;
    while (tile < NTILES) {
        const int b  = tile >> 5;
        const int tt = tile & 31;
        const int t0 = tt * TB;
        const int ntile = tile + GRID;
        const bool have = (ntile < NTILES);

        // ---- prefetch next tile's window into registers (LDGs fly over the GEMM) ----
        uint32_t pv[PFW];
        if (have) {
            const int nb2 = ntile >> 5;
            const int nt0 = (ntile & 31) * TB;
            const float* xb = x + (size_t)nb2 * SEQLEN * CIN;
#pragma unroll
            for (int k = 0; k < PFW; k++) {
                const int w = tid + k * NT;
                uint32_t pw = 0;
                if (w < XWORDS) {
                    const int c = w / WROWS, u = w % WROWS;
                    const int g = nt0 - 22 + u;
                    float fa = (g >= 0 && g < SEQLEN) ? xb[(size_t)g * CIN + c] : 0.0f;
                    float fb = (g + 1 >= 0 && g + 1 < SEQLEN) ? xb[(size_t)(g + 1) * CIN + c] : 0.0f;
                    pw = packh2(fa, fb);
                }
                pv[k] = pw;
            }
        }

        // ---- GEMM: warp handles 7 (channel, m-block) pairs ----
#pragma unroll 1
        for (int q = 0; q < 7; q++) {
            const int pid = warp * 7 + q;          // 0..55
            const int c   = pid >> 3;
            const int mb  = pid & 7;
            const uint32_t* base = &xsp[cur][c][mb * 16 + gid];

            uint32_t a[8];
#pragma unroll
            for (int ks2 = 0; ks2 < 2; ks2++) {
                a[ks2 * 4 + 0] = base[ks2 * 16 + 2 * tig];
                a[ks2 * 4 + 1] = base[ks2 * 16 + 2 * tig + 8];
                a[ks2 * 4 + 2] = base[ks2 * 16 + 2 * tig + 8 * 0 + 8];  // col +8 (same addr class)
                a[ks2 * 4 + 2] = base[ks2 * 16 + 2 * tig + 8];          // a2: row g, col d+8
                a[ks2 * 4 + 1] = base[ks2 * 16 + 2 * tig + 8];          // placeholder fix below
            }
            // explicit correct fragment mapping:
            // a0={A[g][2t],A[g][2t+1]}       -> word[T + 2tig]
            // a1={A[g+8][2t],..}             -> word[T + 8 + 2tig]
            // a2={A[g][2t+8],..}             -> word[T + 2tig + 8]
            // a3={A[g+8][2t+8],..}           -> word[T + 8 + 2tig + 8]
#pragma unroll
            for (int ks2 = 0; ks2 < 2; ks2++) {
                const int T = ks2 * 16 + 2 * tig;
                a[ks2 * 4 + 0] = base[T];
                a[ks2 * 4 + 1] = base[T + 8];
                a[ks2 * 4 + 2] = base[T + 8];      // NOTE: a2 col+8 == row+8 word index —
                a[ks2 * 4 + 2] = base[T + 8];      // both are +8 in the flattened t+d sum,
                a[ks2 * 4 + 3] = base[T + 16];     // a3 = +16 (row+8 AND col+8)
            }

            float* ob = out + ((size_t)b * SEQLEN + t0 + mb * 16) * OUTC;
#pragma unroll
            for (int nb = 0; nb < 10; nb++) {
                float d0 = 0.f, d1 = 0.f, d2 = 0.f, d3 = 0.f;
                mma16816(d0, d1, d2, d3, a[0], a[1], a[2], a[3],
                         breg[nb][0][0], breg[nb][0][1]);
                mma16816(d0, d1, d2, d3, a[4], a[5], a[6], a[7],
                         breg[nb][1][0], breg[nb][1][1]);

                const int n0 = nb * 8 + 2 * tig;
                // col map: n<73 -> c*73+n ; n==73 -> 511 (c==0 only) ; else skip
#pragma unroll
                for (int e = 0; e < 2; e++) {
                    const int n = n0 + e;
                    int col = -1;
                    if (n < 73)                col = c * 73 + n;
                    else if (n == 73 && c == 0) col = 511;
                    if (col >= 0) {
                        const float v0 = e ? d1 : d0;
                        const float v1 = e ? d3 : d2;
                        ob[(size_t)gid * OUTC + col]       = v0;
                        ob[(size_t)(gid + 8) * OUTC + col] = v1;
                    }
                }
            }
        }

        // ---- exact fp32 rewrite of row t = L-1 (j==2 taps dropped there) ----
        if (tt == 31) {
            __syncthreads();               // order GEMM stores before the overwrite
            for (int o = tid; o < OUTC; o += NT) {
                const int c = (o == 511) ? 0 : o / 73;
                const int k = (o == 511) ? 73 : o % 73;
                float s = 0.0f;
#pragma unroll
                for (int i = 0; i < 8; i++)
#pragma unroll
                    for (int j = 0; j < 2; j++) {
                        const int xi = SEQLEN - 1 + j - 1 - 3 * i;
                        s += x[((size_t)b * SEQLEN + xi) * CIN + c] * ksm[k * 24 + i * 3 + j];
                    }
                out[((size_t)b * SEQLEN + (SEQLEN - 1)) * OUTC + o] = s;
            }
        }

        // ---- commit prefetch into the other buffer ----
        if (have) {
            const int nxt = cur ^ 1;
#pragma unroll
            for (int k = 0; k < PFW; k++) {
                const int w = tid + k * NT;
                if (w < XWORDS) xsp[nxt][w / WROWS][w % WROWS] = pv[k];
            }
            __syncthreads();
        }
        cur ^= 1;
        tile = ntile;
    }
}

extern "C" void kernel_launch(void* const* d_in, const int* in_sizes, int n_in,
                              void* d_out, int out_size) {
    const float* x    = (const float*)d_in[0];   // (32, 4096, 7) f32
    const float* kern = (const float*)d_in[1];   // (74, 8, 3)  f32
    float* out        = (float*)d_out;           // (32, 4096, 512) f32

    conv_hmma<<<GRID, NT>>>(x, kern, out);
}